// round 10
// baseline (speedup 1.0000x reference)
#include <cuda_runtime.h>
#include <cuda_bf16.h>

// out[t,b,i,e] = x[t,b,i] * W[i,e] + b[e]
// T=8, B=64, D=512, E=256 -> 268 MB fp32 output. Store-BW bound.
//
// R7 finding: instruction-width changes are invisible; L1 (73%) is BYTES
// bound: previously each output row re-read its 1KB W row through L1, so
// L1 moved ~2x the store bytes. This version is i-major: a block owns one
// W row i and 64 (t,b) rows sharing it. Each warp loads W[i,:] ONCE into
// registers (1 LDG.256/lane) and reuses it for 8 output rows -> W read
// traffic drops ~256x, L1 total bytes ~halve.
//
// Mapping: blockIdx = i*8 + chunk. 8 warps/block; warp w handles
// tb = chunk*64 + w*8 + r (r<8), writing out[(tb*512+i)*256 ..+256).
// Lane owns a 32B chunk (e = lane*8..lane*8+7): one STG.256 per row.

#define D_DIM   512
#define TB_DIM  512                    // T*B = 8*64
#define ROWS_PER_WARP 8
#define WARPS_PER_BLOCK 8
#define THREADS (WARPS_PER_BLOCK * 32)
#define CHUNKS  (TB_DIM / (ROWS_PER_WARP * WARPS_PER_BLOCK))   // 8
#define NBLOCKS (D_DIM * CHUNKS)                               // 4096

__device__ __forceinline__ void ldg256(const float* p, float v[8]) {
    asm volatile("ld.global.nc.v8.f32 {%0,%1,%2,%3,%4,%5,%6,%7}, [%8];"
                 : "=f"(v[0]), "=f"(v[1]), "=f"(v[2]), "=f"(v[3]),
                   "=f"(v[4]), "=f"(v[5]), "=f"(v[6]), "=f"(v[7])
                 : "l"(p));
}

__device__ __forceinline__ void stg256_cs(float* p, const float v[8]) {
    asm volatile("st.global.cs.v8.f32 [%0], {%1,%2,%3,%4,%5,%6,%7,%8};"
                 :: "l"(p),
                    "f"(v[0]), "f"(v[1]), "f"(v[2]), "f"(v[3]),
                    "f"(v[4]), "f"(v[5]), "f"(v[6]), "f"(v[7])
                 : "memory");
}

__global__ __launch_bounds__(THREADS)
void dense_embed_kernel(const float* __restrict__ x,
                        const float* __restrict__ W,
                        const float* __restrict__ b,
                        float* __restrict__ out)
{
    unsigned i     = blockIdx.x >> 3;            // W row, < 512
    unsigned chunk = blockIdx.x & 7;
    unsigned warp  = threadIdx.x >> 5;
    unsigned lane  = threadIdx.x & 31;
    unsigned eoff  = lane << 3;                  // lane*8 floats = 32B chunk
    unsigned tb0   = chunk * (ROWS_PER_WARP * WARPS_PER_BLOCK)
                   + warp * ROWS_PER_WARP;       // first tb for this warp

    // Load W row i and bias ONCE; reuse for all 8 rows.
    float wv[8], bb[8];
    ldg256(W + (i << 8) + eoff, wv);
    ldg256(b + eoff, bb);

    // Front-batch the 8 uniform x loads.
    float xv[ROWS_PER_WARP];
    #pragma unroll
    for (int r = 0; r < ROWS_PER_WARP; ++r)
        xv[r] = __ldg(&x[(tb0 + r) * D_DIM + i]);

    #pragma unroll
    for (int r = 0; r < ROWS_PER_WARP; ++r) {
        float o[8];
        #pragma unroll
        for (int k = 0; k < 8; ++k)
            o[k] = fmaf(xv[r], wv[k], bb[k]);

        // out row = tb*512 + i ; byte-contiguous 1KB per row
        float* orow = out + (((unsigned long long)(tb0 + r) << 17)
                             + ((unsigned long long)i << 8));
        stg256_cs(orow + eoff, o);
    }
}

extern "C" void kernel_launch(void* const* d_in, const int* in_sizes, int n_in,
                              void* d_out, int out_size)
{
    const float* x = (const float*)d_in[0];
    const float* W = (const float*)d_in[1];
    const float* b = (const float*)d_in[2];
    float* out = (float*)d_out;

    dense_embed_kernel<<<NBLOCKS, THREADS>>>(x, W, b, out);
}

// round 12
// speedup vs baseline: 1.0249x; 1.0249x over previous
#include <cuda_runtime.h>
#include <cuda_bf16.h>

// out[t,b,i,e] = x[t,b,i] * W[i,e] + b[e]
// T=8, B=64, D=512, E=256 -> 268 MB fp32 output.
//
// R10 finding: three different structures all pin at 39.8-40.9us,
// DRAM ~65%, L1 ~70-73% regardless of read traffic -> bound by the DRAM
// write path itself (~5.2 TB/s achieved). Only untested store-path
// variable: cache policy. All prior runs used .cs (evict-first).
// This run: IDENTICAL to the fastest kernel (R7 row-major v8, 39.81us)
// but with DEFAULT write-back stores, letting L2 aggregate full dirty
// lines and drain HBM in larger bursts.

#define D_DIM  512
#define NROWS  (8 * 64 * 512)            // 262144 rows
#define ROWS_PER_WARP 4
#define WARPS_PER_BLOCK 8
#define THREADS (WARPS_PER_BLOCK * 32)
#define NBLOCKS (NROWS / (ROWS_PER_WARP * WARPS_PER_BLOCK))   // 8192

__device__ __forceinline__ void ldg256(const float* p, float v[8]) {
    asm volatile("ld.global.nc.v8.f32 {%0,%1,%2,%3,%4,%5,%6,%7}, [%8];"
                 : "=f"(v[0]), "=f"(v[1]), "=f"(v[2]), "=f"(v[3]),
                   "=f"(v[4]), "=f"(v[5]), "=f"(v[6]), "=f"(v[7])
                 : "l"(p));
}

__device__ __forceinline__ void stg256(float* p, const float v[8]) {
    asm volatile("st.global.v8.f32 [%0], {%1,%2,%3,%4,%5,%6,%7,%8};"
                 :: "l"(p),
                    "f"(v[0]), "f"(v[1]), "f"(v[2]), "f"(v[3]),
                    "f"(v[4]), "f"(v[5]), "f"(v[6]), "f"(v[7])
                 : "memory");
}

__global__ __launch_bounds__(THREADS)
void dense_embed_kernel(const float* __restrict__ x,
                        const float* __restrict__ W,
                        const float* __restrict__ b,
                        float* __restrict__ out)
{
    unsigned warp_id = blockIdx.x * WARPS_PER_BLOCK + (threadIdx.x >> 5);
    unsigned lane    = threadIdx.x & 31;
    unsigned row0    = warp_id * ROWS_PER_WARP;
    unsigned eoff    = lane << 3;                 // lane*8 floats = 32B chunk

    float bb[8];
    ldg256(b + eoff, bb);

    // Front-batch all loads, then all stores.
    float xv[ROWS_PER_WARP];
    float wv[ROWS_PER_WARP][8];

    #pragma unroll
    for (int r = 0; r < ROWS_PER_WARP; ++r) {
        unsigned row = row0 + r;
        unsigned i   = row & (D_DIM - 1);         // row % 512
        xv[r] = __ldg(&x[row]);                   // uniform broadcast
        ldg256(W + (i << 8) + eoff, wv[r]);       // W row = 256 floats
    }

    #pragma unroll
    for (int r = 0; r < ROWS_PER_WARP; ++r) {
        float o[8];
        #pragma unroll
        for (int k = 0; k < 8; ++k)
            o[k] = fmaf(xv[r], wv[r][k], bb[k]);

        float* orow = out + (((unsigned long long)(row0 + r)) << 8);
        stg256(orow + eoff, o);
    }
}

extern "C" void kernel_launch(void* const* d_in, const int* in_sizes, int n_in,
                              void* d_out, int out_size)
{
    const float* x = (const float*)d_in[0];
    const float* W = (const float*)d_in[1];
    const float* b = (const float*)d_in[2];
    float* out = (float*)d_out;

    dense_embed_kernel<<<NBLOCKS, THREADS>>>(x, W, b, out);
}